// round 1
// baseline (speedup 1.0000x reference)
#include <cuda_runtime.h>
#include <cstdint>
#include <cstddef>

#define NN   8192
#define HID  64
#define NWRD 256          // 8192/32 mask words per row

// -------- device-global scratch (no allocs allowed) --------
__device__ unsigned g_bits[NN * NWRD];   // 8 MB adjacency bitmask (L2-resident)
__device__ float    g_dinv[NN];
__device__ float4   g_sst[NN];           // dinv[j] * states[j][0..3]
__device__ float    g_y2[NN * HID];      // dinv[j] * (h1[j] @ W2)

__device__ __forceinline__ float2 f2add(float2 a, float2 b) {
    unsigned long long ua = *reinterpret_cast<unsigned long long*>(&a);
    unsigned long long ub = *reinterpret_cast<unsigned long long*>(&b);
    unsigned long long ur;
    asm("add.rn.f32x2 %0, %1, %2;" : "=l"(ur) : "l"(ua), "l"(ub));
    float2 r;
    *reinterpret_cast<unsigned long long*>(&r) = ur;
    return r;
}

// ============================================================
// Pass A: pair distance checks -> mask floats + bitmask + degrees
// block = 256 threads, 16 rows per block, grid = 512
// ============================================================
__global__ void __launch_bounds__(256) kA(const float4* __restrict__ st,
                                          float* __restrict__ omask) {
    extern __shared__ __align__(16) char smemA[];
    float2* spos = (float2*)smemA;               // 64 KB
    int*    sdeg = (int*)(spos + NN);

    const int t    = threadIdx.x;
    const int lane = t & 31;

    for (int j = t; j < NN; j += 256) {
        float4 s = st[j];
        spos[j] = make_float2(s.x, s.y);
    }
    if (t < 16) sdeg[t] = 0;
    __syncthreads();

    const int row0 = blockIdx.x << 4;
    const float4* sp4 = (const float4*)spos;

    for (int r = 0; r < 16; ++r) {
        const int i = row0 + r;
        const float xi = spos[i].x, yi = spos[i].y;
        int cnt = 0;
#pragma unroll
        for (int c = 0; c < 8; ++c) {
            const int j = (c << 10) + (t << 2);      // 4 consecutive js
            float4 p01 = sp4[j >> 1];
            float4 p23 = sp4[(j >> 1) + 1];

            float dx0 = __fsub_rn(xi, p01.x), dy0 = __fsub_rn(yi, p01.y);
            float dx1 = __fsub_rn(xi, p01.z), dy1 = __fsub_rn(yi, p01.w);
            float dx2 = __fsub_rn(xi, p23.x), dy2 = __fsub_rn(yi, p23.y);
            float dx3 = __fsub_rn(xi, p23.z), dy3 = __fsub_rn(yi, p23.w);

            float d0 = __fadd_rn(__fmul_rn(dx0, dx0), __fmul_rn(dy0, dy0));
            float d1 = __fadd_rn(__fmul_rn(dx1, dx1), __fmul_rn(dy1, dy1));
            float d2 = __fadd_rn(__fmul_rn(dx2, dx2), __fmul_rn(dy2, dy2));
            float d3 = __fadd_rn(__fmul_rn(dx3, dx3), __fmul_rn(dy3, dy3));

            unsigned m0 = (d0 <= 1.0f) ? 1u : 0u;
            unsigned m1 = (d1 <= 1.0f) ? 1u : 0u;
            unsigned m2 = (d2 <= 1.0f) ? 1u : 0u;
            unsigned m3 = (d3 <= 1.0f) ? 1u : 0u;

            float4 mf = make_float4(m0 ? 1.f : 0.f, m1 ? 1.f : 0.f,
                                    m2 ? 1.f : 0.f, m3 ? 1.f : 0.f);
            *reinterpret_cast<float4*>(omask + (size_t)i * NN + j) = mf;

            unsigned nib = m0 | (m1 << 1) | (m2 << 2) | (m3 << 3);
            cnt += (int)(m0 + m1 + m2 + m3);

            unsigned v = nib << ((lane & 7) * 4);
            v |= __shfl_xor_sync(0xffffffffu, v, 1);
            v |= __shfl_xor_sync(0xffffffffu, v, 2);
            v |= __shfl_xor_sync(0xffffffffu, v, 4);
            if ((lane & 7) == 0) {
                const int jb = (c << 10) + ((t >> 5) << 7);   // warp j base
                g_bits[i * NWRD + (jb >> 5) + (lane >> 3)] = v;
            }
        }
#pragma unroll
        for (int o = 16; o; o >>= 1) cnt += __shfl_xor_sync(0xffffffffu, cnt, o);
        if (lane == 0) atomicAdd(&sdeg[r], cnt);
    }
    __syncthreads();

    if (t < 16) {
        const int i = row0 + t;
        const float dinv = 1.0f / sqrtf((float)sdeg[t]);
        g_dinv[i] = dinv;
        float4 s = st[i];
        g_sst[i] = make_float4(dinv * s.x, dinv * s.y, dinv * s.z, dinv * s.w);
    }
}

// ============================================================
// Pass B: AS = A_norm @ states (4-wide sparse), h1 = relu(AS@W1+b1),
//         y2' = dinv_i * (h1 @ W2).  warp-per-row, grid = 256 x 1024
// ============================================================
__global__ void __launch_bounds__(1024) kB(const float* __restrict__ W1,
                                           const float* __restrict__ b1,
                                           const float* __restrict__ W2) {
    extern __shared__ __align__(16) char smemB[];
    float4* ss   = (float4*)smemB;                 // 128 KB pre-scaled states
    float*  w2s  = (float*)(ss + NN);              // 16 KB
    float*  w1s  = w2s + HID * HID;                // 1 KB
    float*  b1s  = w1s + 4 * HID;
    float*  rowb = b1s + HID;                      // 32 warps * 64 = 8 KB

    const int t = threadIdx.x, lane = t & 31, wp = t >> 5;

    for (int k = t; k < NN; k += 1024)       ss[k]  = g_sst[k];
    for (int k = t; k < HID * HID; k += 1024) w2s[k] = W2[k];
    if (t < 4 * HID) w1s[t] = W1[t];
    if (t < HID)     b1s[t] = b1[t];
    __syncthreads();

    const int i = (blockIdx.x << 5) + wp;
    float4 acc = make_float4(0.f, 0.f, 0.f, 0.f);
    const unsigned base = (unsigned)i * NWRD;

#pragma unroll
    for (int ww = 0; ww < 8; ++ww) {
        const int w = lane + (ww << 5);
        unsigned bits = g_bits[base + w];
        const int jb = w << 5;
        while (bits) {
            const int b = __ffs(bits) - 1;
            bits &= bits - 1;
            float4 v = ss[jb + b];
            acc.x += v.x; acc.y += v.y; acc.z += v.z; acc.w += v.w;
        }
    }
#pragma unroll
    for (int o = 16; o; o >>= 1) {
        acc.x += __shfl_xor_sync(0xffffffffu, acc.x, o);
        acc.y += __shfl_xor_sync(0xffffffffu, acc.y, o);
        acc.z += __shfl_xor_sync(0xffffffffu, acc.z, o);
        acc.w += __shfl_xor_sync(0xffffffffu, acc.w, o);
    }

    const float dinv = g_dinv[i];
    const float ax = acc.x * dinv, ay = acc.y * dinv,
                az = acc.z * dinv, aw = acc.w * dinv;

    // h1 dims: lane and lane+32
    float ha = b1s[lane] + ax * w1s[lane] + ay * w1s[HID + lane]
             + az * w1s[2 * HID + lane] + aw * w1s[3 * HID + lane];
    float hb = b1s[lane + 32] + ax * w1s[lane + 32] + ay * w1s[HID + lane + 32]
             + az * w1s[2 * HID + lane + 32] + aw * w1s[3 * HID + lane + 32];
    ha = fmaxf(ha, 0.f);
    hb = fmaxf(hb, 0.f);
    rowb[wp * HID + lane]      = ha;
    rowb[wp * HID + lane + 32] = hb;
    __syncwarp();

    const int e = lane << 1;
    float yx = 0.f, yy = 0.f;
#pragma unroll 8
    for (int k = 0; k < HID; ++k) {
        const float hk = rowb[wp * HID + k];
        yx += hk * w2s[k * HID + e];
        yy += hk * w2s[k * HID + e + 1];
    }
    *reinterpret_cast<float2*>(&g_y2[i * HID + e]) =
        make_float2(dinv * yx, dinv * yy);
}

// ============================================================
// Pass C: acc = sum over masked j of y2'[j] (64-wide), then
//         h2 = relu(dinv_i*acc + b2), out = h2 . cw + cb
// warp-per-row, y2' staged through SMEM in 512-row tiles.
// grid = 256 x 1024
// ============================================================
__global__ void __launch_bounds__(1024) kC(const float* __restrict__ b2,
                                           const float* __restrict__ cw,
                                           const float* __restrict__ cb,
                                           float* __restrict__ dout) {
    extern __shared__ __align__(16) char smemC[];
    float* yt  = (float*)smemC;            // 512*64 floats = 128 KB
    float* b2s = yt + 512 * HID;
    float* cws = b2s + HID;

    const int t = threadIdx.x, lane = t & 31, wp = t >> 5;
    if (t < HID) { b2s[t] = b2[t]; cws[t] = cw[t]; }

    const int i = (blockIdx.x << 5) + wp;
    float2 acc = make_float2(0.f, 0.f);
    const float4* gy4 = (const float4*)g_y2;
    float4* yt4 = (float4*)yt;
    const unsigned rbase = (unsigned)i * NWRD;

    for (int tl = 0; tl < 16; ++tl) {
        __syncthreads();
#pragma unroll
        for (int k = 0; k < 8; ++k)
            yt4[t + (k << 10)] = gy4[(tl << 13) + t + (k << 10)];
        __syncthreads();

        unsigned wv = 0;
        if (lane < 16) wv = g_bits[rbase + (tl << 4) + lane];

#pragma unroll
        for (int w = 0; w < 16; ++w) {
            unsigned bits = __shfl_sync(0xffffffffu, wv, w);
            const float* ybase = yt + ((w << 5) << 6) + (lane << 1);
            while (bits) {
                const int b = __ffs(bits) - 1;
                bits &= bits - 1;
                float2 v = *reinterpret_cast<const float2*>(ybase + (b << 6));
                acc = f2add(acc, v);
            }
        }
    }

    const float dinv = g_dinv[i];
    const int e = lane << 1;
    const float h0 = fmaxf(b2s[e]     + dinv * acc.x, 0.f);
    const float h1 = fmaxf(b2s[e + 1] + dinv * acc.y, 0.f);
    float p = h0 * cws[e] + h1 * cws[e + 1];
#pragma unroll
    for (int o = 16; o; o >>= 1) p += __shfl_xor_sync(0xffffffffu, p, o);
    if (lane == 0) dout[i] = p + cb[0];
}

// ============================================================
extern "C" void kernel_launch(void* const* d_in, const int* in_sizes, int n_in,
                              void* d_out, int out_size) {
    const float* states = (const float*)d_in[0];
    const float* W1     = (const float*)d_in[1];
    const float* b1     = (const float*)d_in[2];
    const float* W2     = (const float*)d_in[3];
    const float* b2     = (const float*)d_in[4];
    const float* cw     = (const float*)d_in[5];
    const float* cb     = (const float*)d_in[6];
    float* out = (float*)d_out;

    const int smemA = NN * (int)sizeof(float2) + 16 * (int)sizeof(int);
    const int smemB = NN * (int)sizeof(float4) + (HID * HID + 4 * HID + HID + 32 * HID) * (int)sizeof(float);
    const int smemC = (512 * HID + 2 * HID) * (int)sizeof(float);

    cudaFuncSetAttribute(kA, cudaFuncAttributeMaxDynamicSharedMemorySize, smemA);
    cudaFuncSetAttribute(kB, cudaFuncAttributeMaxDynamicSharedMemorySize, smemB);
    cudaFuncSetAttribute(kC, cudaFuncAttributeMaxDynamicSharedMemorySize, smemC);

    kA<<<512, 256, smemA>>>((const float4*)states, out + NN);
    kB<<<256, 1024, smemB>>>(W1, b1, W2);
    kC<<<256, 1024, smemC>>>(b2, cw, cb, out);
}

// round 2
// speedup vs baseline: 1.0010x; 1.0010x over previous
#include <cuda_runtime.h>
#include <cstdint>
#include <cstddef>

#define NN   8192
#define HID  64
#define NWRD 256          // 8192/32 mask words per row

// -------- device-global scratch (no allocs allowed) --------
__device__ unsigned g_bits[NN * NWRD];   // 8 MB adjacency bitmask (L2-resident)
__device__ float    g_dinv[NN];
__device__ float4   g_sst[NN];           // dinv[j] * states[j][0..3]
__device__ float    g_y2[NN * HID];      // dinv[j] * (h1[j] @ W2)

__device__ __forceinline__ float2 f2add(float2 a, float2 b) {
    unsigned long long ua = *reinterpret_cast<unsigned long long*>(&a);
    unsigned long long ub = *reinterpret_cast<unsigned long long*>(&b);
    unsigned long long ur;
    asm("add.rn.f32x2 %0, %1, %2;" : "=l"(ur) : "l"(ua), "l"(ub));
    float2 r;
    *reinterpret_cast<unsigned long long*>(&r) = ur;
    return r;
}

// ============================================================
// Pass A: pair distance checks -> mask floats + bitmask + degrees
// block = 256 threads, 16 rows per block, grid = 512
// ============================================================
__global__ void __launch_bounds__(256) kA(const float4* __restrict__ st,
                                          float* __restrict__ omask) {
    extern __shared__ __align__(16) char smemA[];
    float2* spos = (float2*)smemA;               // 64 KB
    int*    sdeg = (int*)(spos + NN);

    const int t    = threadIdx.x;
    const int lane = t & 31;

    for (int j = t; j < NN; j += 256) {
        float4 s = st[j];
        spos[j] = make_float2(s.x, s.y);
    }
    if (t < 16) sdeg[t] = 0;
    __syncthreads();

    const int row0 = blockIdx.x << 4;
    const float4* sp4 = (const float4*)spos;

    for (int r = 0; r < 16; ++r) {
        const int i = row0 + r;
        const float xi = spos[i].x, yi = spos[i].y;
        int cnt = 0;
#pragma unroll
        for (int c = 0; c < 8; ++c) {
            const int j = (c << 10) + (t << 2);      // 4 consecutive js
            float4 p01 = sp4[j >> 1];
            float4 p23 = sp4[(j >> 1) + 1];

            float dx0 = __fsub_rn(xi, p01.x), dy0 = __fsub_rn(yi, p01.y);
            float dx1 = __fsub_rn(xi, p01.z), dy1 = __fsub_rn(yi, p01.w);
            float dx2 = __fsub_rn(xi, p23.x), dy2 = __fsub_rn(yi, p23.y);
            float dx3 = __fsub_rn(xi, p23.z), dy3 = __fsub_rn(yi, p23.w);

            float d0 = __fadd_rn(__fmul_rn(dx0, dx0), __fmul_rn(dy0, dy0));
            float d1 = __fadd_rn(__fmul_rn(dx1, dx1), __fmul_rn(dy1, dy1));
            float d2 = __fadd_rn(__fmul_rn(dx2, dx2), __fmul_rn(dy2, dy2));
            float d3 = __fadd_rn(__fmul_rn(dx3, dx3), __fmul_rn(dy3, dy3));

            unsigned m0 = (d0 <= 1.0f) ? 1u : 0u;
            unsigned m1 = (d1 <= 1.0f) ? 1u : 0u;
            unsigned m2 = (d2 <= 1.0f) ? 1u : 0u;
            unsigned m3 = (d3 <= 1.0f) ? 1u : 0u;

            float4 mf = make_float4(m0 ? 1.f : 0.f, m1 ? 1.f : 0.f,
                                    m2 ? 1.f : 0.f, m3 ? 1.f : 0.f);
            *reinterpret_cast<float4*>(omask + (size_t)i * NN + j) = mf;

            unsigned nib = m0 | (m1 << 1) | (m2 << 2) | (m3 << 3);
            cnt += (int)(m0 + m1 + m2 + m3);

            unsigned v = nib << ((lane & 7) * 4);
            v |= __shfl_xor_sync(0xffffffffu, v, 1);
            v |= __shfl_xor_sync(0xffffffffu, v, 2);
            v |= __shfl_xor_sync(0xffffffffu, v, 4);
            if ((lane & 7) == 0) {
                const int jb = (c << 10) + ((t >> 5) << 7);   // warp j base
                g_bits[i * NWRD + (jb >> 5) + (lane >> 3)] = v;
            }
        }
#pragma unroll
        for (int o = 16; o; o >>= 1) cnt += __shfl_xor_sync(0xffffffffu, cnt, o);
        if (lane == 0) atomicAdd(&sdeg[r], cnt);
    }
    __syncthreads();

    if (t < 16) {
        const int i = row0 + t;
        const float dinv = 1.0f / sqrtf((float)sdeg[t]);
        g_dinv[i] = dinv;
        float4 s = st[i];
        g_sst[i] = make_float4(dinv * s.x, dinv * s.y, dinv * s.z, dinv * s.w);
    }
}

// ============================================================
// Pass B: AS = A_norm @ states (4-wide sparse), h1 = relu(AS@W1+b1),
//         y2' = dinv_i * (h1 @ W2).  warp-per-row, grid = 256 x 1024
// ============================================================
__global__ void __launch_bounds__(1024) kB(const float* __restrict__ W1,
                                           const float* __restrict__ b1,
                                           const float* __restrict__ W2) {
    extern __shared__ __align__(16) char smemB[];
    float4* ss   = (float4*)smemB;                 // 128 KB pre-scaled states
    float*  w2s  = (float*)(ss + NN);              // 16 KB
    float*  w1s  = w2s + HID * HID;                // 1 KB
    float*  b1s  = w1s + 4 * HID;
    float*  rowb = b1s + HID;                      // 32 warps * 64 = 8 KB

    const int t = threadIdx.x, lane = t & 31, wp = t >> 5;

    for (int k = t; k < NN; k += 1024)       ss[k]  = g_sst[k];
    for (int k = t; k < HID * HID; k += 1024) w2s[k] = W2[k];
    if (t < 4 * HID) w1s[t] = W1[t];
    if (t < HID)     b1s[t] = b1[t];
    __syncthreads();

    const int i = (blockIdx.x << 5) + wp;
    float4 acc = make_float4(0.f, 0.f, 0.f, 0.f);
    const unsigned base = (unsigned)i * NWRD;

#pragma unroll
    for (int ww = 0; ww < 8; ++ww) {
        const int w = lane + (ww << 5);
        unsigned bits = g_bits[base + w];
        const int jb = w << 5;
        while (bits) {
            const int b = __ffs(bits) - 1;
            bits &= bits - 1;
            float4 v = ss[jb + b];
            acc.x += v.x; acc.y += v.y; acc.z += v.z; acc.w += v.w;
        }
    }
#pragma unroll
    for (int o = 16; o; o >>= 1) {
        acc.x += __shfl_xor_sync(0xffffffffu, acc.x, o);
        acc.y += __shfl_xor_sync(0xffffffffu, acc.y, o);
        acc.z += __shfl_xor_sync(0xffffffffu, acc.z, o);
        acc.w += __shfl_xor_sync(0xffffffffu, acc.w, o);
    }

    const float dinv = g_dinv[i];
    const float ax = acc.x * dinv, ay = acc.y * dinv,
                az = acc.z * dinv, aw = acc.w * dinv;

    // h1 dims: lane and lane+32
    float ha = b1s[lane] + ax * w1s[lane] + ay * w1s[HID + lane]
             + az * w1s[2 * HID + lane] + aw * w1s[3 * HID + lane];
    float hb = b1s[lane + 32] + ax * w1s[lane + 32] + ay * w1s[HID + lane + 32]
             + az * w1s[2 * HID + lane + 32] + aw * w1s[3 * HID + lane + 32];
    ha = fmaxf(ha, 0.f);
    hb = fmaxf(hb, 0.f);
    rowb[wp * HID + lane]      = ha;
    rowb[wp * HID + lane + 32] = hb;
    __syncwarp();

    const int e = lane << 1;
    float yx = 0.f, yy = 0.f;
#pragma unroll 8
    for (int k = 0; k < HID; ++k) {
        const float hk = rowb[wp * HID + k];
        yx += hk * w2s[k * HID + e];
        yy += hk * w2s[k * HID + e + 1];
    }
    *reinterpret_cast<float2*>(&g_y2[i * HID + e]) =
        make_float2(dinv * yx, dinv * yy);
}

// ============================================================
// Pass C: acc = sum over masked j of y2'[j] (64-wide), then
//         h2 = relu(dinv_i*acc + b2), out = h2 . cw + cb
// warp-per-row, y2' staged through SMEM in 512-row tiles.
// grid = 256 x 1024
// ============================================================
__global__ void __launch_bounds__(1024) kC(const float* __restrict__ b2,
                                           const float* __restrict__ cw,
                                           const float* __restrict__ cb,
                                           float* __restrict__ dout) {
    extern __shared__ __align__(16) char smemC[];
    float* yt  = (float*)smemC;            // 512*64 floats = 128 KB
    float* b2s = yt + 512 * HID;
    float* cws = b2s + HID;

    const int t = threadIdx.x, lane = t & 31, wp = t >> 5;
    if (t < HID) { b2s[t] = b2[t]; cws[t] = cw[t]; }

    const int i = (blockIdx.x << 5) + wp;
    float2 acc = make_float2(0.f, 0.f);
    const float4* gy4 = (const float4*)g_y2;
    float4* yt4 = (float4*)yt;
    const unsigned rbase = (unsigned)i * NWRD;

    for (int tl = 0; tl < 16; ++tl) {
        __syncthreads();
#pragma unroll
        for (int k = 0; k < 8; ++k)
            yt4[t + (k << 10)] = gy4[(tl << 13) + t + (k << 10)];
        __syncthreads();

        unsigned wv = 0;
        if (lane < 16) wv = g_bits[rbase + (tl << 4) + lane];

#pragma unroll
        for (int w = 0; w < 16; ++w) {
            unsigned bits = __shfl_sync(0xffffffffu, wv, w);
            const float* ybase = yt + ((w << 5) << 6) + (lane << 1);
            while (bits) {
                const int b = __ffs(bits) - 1;
                bits &= bits - 1;
                float2 v = *reinterpret_cast<const float2*>(ybase + (b << 6));
                acc = f2add(acc, v);
            }
        }
    }

    const float dinv = g_dinv[i];
    const int e = lane << 1;
    const float h0 = fmaxf(b2s[e]     + dinv * acc.x, 0.f);
    const float h1 = fmaxf(b2s[e + 1] + dinv * acc.y, 0.f);
    float p = h0 * cws[e] + h1 * cws[e + 1];
#pragma unroll
    for (int o = 16; o; o >>= 1) p += __shfl_xor_sync(0xffffffffu, p, o);
    if (lane == 0) dout[i] = p + cb[0];
}

// ============================================================
extern "C" void kernel_launch(void* const* d_in, const int* in_sizes, int n_in,
                              void* d_out, int out_size) {
    const float* states = (const float*)d_in[0];
    const float* W1     = (const float*)d_in[1];
    const float* b1     = (const float*)d_in[2];
    const float* W2     = (const float*)d_in[3];
    const float* b2     = (const float*)d_in[4];
    const float* cw     = (const float*)d_in[5];
    const float* cb     = (const float*)d_in[6];
    float* out = (float*)d_out;

    const int smemA = NN * (int)sizeof(float2) + 16 * (int)sizeof(int);
    const int smemB = NN * (int)sizeof(float4) + (HID * HID + 4 * HID + HID + 32 * HID) * (int)sizeof(float);
    const int smemC = (512 * HID + 2 * HID) * (int)sizeof(float);

    cudaFuncSetAttribute(kA, cudaFuncAttributeMaxDynamicSharedMemorySize, smemA);
    cudaFuncSetAttribute(kB, cudaFuncAttributeMaxDynamicSharedMemorySize, smemB);
    cudaFuncSetAttribute(kC, cudaFuncAttributeMaxDynamicSharedMemorySize, smemC);

    kA<<<512, 256, smemA>>>((const float4*)states, out + NN);
    kB<<<256, 1024, smemB>>>(W1, b1, W2);
    kC<<<256, 1024, smemC>>>(b2, cw, cb, out);
}